// round 4
// baseline (speedup 1.0000x reference)
#include <cuda_runtime.h>
#include <math.h>

#define N_AREA 10000
#define N_FEAT 16
#define HID    64
#define N_EDGE 320000
#define BATCH  64
#define ETOT   (N_EDGE + N_AREA)
#define ROWF   (BATCH * HID)          /* 4096 floats per node row */
#define STATE_ROW (N_AREA * N_FEAT)   /* 160000 floats per batch row of state */

// ---------------- scratch (device globals; no allocations allowed) ----------
__device__ int   g_deg[N_AREA];
__device__ float g_dinv[N_AREA];
__device__ int   g_rowptr[N_AREA + 1];
__device__ int   g_cursor[N_AREA];
__device__ int   g_col[ETOT];
__device__ float g_w[ETOT];
__device__ float g_h1[(size_t)N_AREA * ROWF];   // 164 MB
__device__ float g_h2[(size_t)N_AREA * ROWF];   // 164 MB

__device__ __forceinline__ void fma4(float4& a, float w, float4 v) {
    a.x += w * v.x; a.y += w * v.y; a.z += w * v.z; a.w += w * v.w;
}
__device__ __forceinline__ float lrelu(float x) { return x >= 0.f ? x : 0.01f * x; }

#define FMA16(o, a, wr) do { \
    float4 w0_ = (wr)[0], w1_ = (wr)[1], w2_ = (wr)[2], w3_ = (wr)[3]; \
    (o)[0]  += (a) * w0_.x; (o)[1]  += (a) * w0_.y; (o)[2]  += (a) * w0_.z; (o)[3]  += (a) * w0_.w; \
    (o)[4]  += (a) * w1_.x; (o)[5]  += (a) * w1_.y; (o)[6]  += (a) * w1_.z; (o)[7]  += (a) * w1_.w; \
    (o)[8]  += (a) * w2_.x; (o)[9]  += (a) * w2_.y; (o)[10] += (a) * w2_.z; (o)[11] += (a) * w2_.w; \
    (o)[12] += (a) * w3_.x; (o)[13] += (a) * w3_.y; (o)[14] += (a) * w3_.z; (o)[15] += (a) * w3_.w; \
} while (0)

// ---------------- CSR / norm construction ----------------------------------
__global__ void k_initdeg() {
    int i = blockIdx.x * blockDim.x + threadIdx.x;
    if (i < N_AREA) g_deg[i] = 1;   // self-loop
}
__global__ void k_count(const int* __restrict__ ei) {
    int e = blockIdx.x * blockDim.x + threadIdx.x;
    if (e < N_EDGE) atomicAdd(&g_deg[ei[N_EDGE + e]], 1);
}
__global__ void k_dinv() {
    int i = blockIdx.x * blockDim.x + threadIdx.x;
    if (i < N_AREA) g_dinv[i] = rsqrtf((float)g_deg[i]);
}
// single-block scan: row_ptr (inclusive shifted) + cursor (= row start)
__global__ void k_scan() {
    __shared__ int wsum[32];
    __shared__ int btot_s;
    int tid = threadIdx.x, lane = tid & 31, wid = tid >> 5;
    int offset = 0;
    for (int base = 0; base < N_AREA; base += 1024) {
        int i = base + tid;
        int v = (i < N_AREA) ? g_deg[i] : 0;
        int x = v;
        #pragma unroll
        for (int d = 1; d < 32; d <<= 1) {
            int y = __shfl_up_sync(0xffffffffu, x, d);
            if (lane >= d) x += y;
        }
        if (lane == 31) wsum[wid] = x;
        __syncthreads();
        if (wid == 0) {
            int s = wsum[lane];
            #pragma unroll
            for (int d = 1; d < 32; d <<= 1) {
                int y = __shfl_up_sync(0xffffffffu, s, d);
                if (lane >= d) s += y;
            }
            wsum[lane] = s;
            if (lane == 31) btot_s = s;
        }
        __syncthreads();
        int incl = x + (wid > 0 ? wsum[wid - 1] : 0) + offset;
        if (i < N_AREA) { g_rowptr[i + 1] = incl; g_cursor[i] = incl - v; }
        offset += btot_s;
        __syncthreads();
    }
    if (tid == 0) g_rowptr[0] = 0;
}
__global__ void k_fill(const int* __restrict__ ei) {
    int e = blockIdx.x * blockDim.x + threadIdx.x;
    if (e < N_EDGE) {
        int s = ei[e], d = ei[N_EDGE + e];
        int pos = atomicAdd(&g_cursor[d], 1);
        g_col[pos] = s;
        g_w[pos] = g_dinv[s] * g_dinv[d];
    } else if (e < ETOT) {
        int n = e - N_EDGE;
        int pos = atomicAdd(&g_cursor[n], 1);
        g_col[pos] = n;
        float dv = g_dinv[n];
        g_w[pos] = dv * dv;
    }
}

// ---------------- layer 1: agg(x) -> @W1 -> +b1 -> LN(g1,be1) -> leaky -> h1
__global__ __launch_bounds__(256) void k_layer1(
    const float* __restrict__ state, const float* __restrict__ W1,
    const float* __restrict__ b1, const float* __restrict__ g1,
    const float* __restrict__ be1)
{
    __shared__ float W1s[N_FEAT * HID];   // 1024 floats
    __shared__ float aggs[BATCH * 20];    // [64][16+4pad]
    const int n = blockIdx.x, t = threadIdx.x;
    ((float4*)W1s)[t] = ((const float4*)W1)[t];   // 256 float4 exactly

    // gather: thread t owns (b=t/4, f0=(t%4)*4 .. +3) of the [B,F] agg row
    const int b = t >> 2, f0 = (t & 3) * 4;
    const float4* __restrict__ base =
        (const float4*)(state + (size_t)b * STATE_ROW + f0);
    float4 acc = make_float4(0.f, 0.f, 0.f, 0.f);
    const int e0 = g_rowptr[n], e1 = g_rowptr[n + 1];
    int e = e0;
    for (; e + 1 < e1; e += 2) {
        int   s0 = g_col[e],  s1 = g_col[e + 1];
        float w0 = g_w[e],    w1 = g_w[e + 1];
        float4 v0 = base[(size_t)s0 * 4];
        float4 v1 = base[(size_t)s1 * 4];
        fma4(acc, w0, v0);
        fma4(acc, w1, v1);
    }
    if (e < e1) {
        int s0 = g_col[e]; float w0 = g_w[e];
        fma4(acc, w0, base[(size_t)s0 * 4]);
    }
    *(float4*)&aggs[b * 20 + f0] = acc;
    __syncthreads();

    // GEMM 16->64 + bias + LN + leaky ; thread -> (b, j0=(t%4)*16 .. +15)
    const int j0 = (t & 3) * 16;
    float o[16];
    #pragma unroll
    for (int i = 0; i < 16; i++) o[i] = 0.f;
    #pragma unroll
    for (int f = 0; f < N_FEAT; f++) {
        float a = aggs[b * 20 + f];
        const float4* wr = (const float4*)(W1s + f * HID + j0);
        FMA16(o, a, wr);
    }
    #pragma unroll
    for (int i = 0; i < 16; i++) o[i] += b1[j0 + i];
    float s1 = 0.f, s2 = 0.f;
    #pragma unroll
    for (int i = 0; i < 16; i++) { s1 += o[i]; s2 += o[i] * o[i]; }
    s1 += __shfl_xor_sync(0xffffffffu, s1, 1);
    s1 += __shfl_xor_sync(0xffffffffu, s1, 2);
    s2 += __shfl_xor_sync(0xffffffffu, s2, 1);
    s2 += __shfl_xor_sync(0xffffffffu, s2, 2);
    float mu  = s1 * (1.f / HID);
    float var = s2 * (1.f / HID) - mu * mu;
    float rs  = rsqrtf(var + 1e-5f);
    #pragma unroll
    for (int i = 0; i < 16; i++) {
        float v = (o[i] - mu) * rs * g1[j0 + i] + be1[j0 + i];
        o[i] = lrelu(v);
    }
    float* dstp = g_h1 + (size_t)n * ROWF + b * HID + j0;
    #pragma unroll
    for (int i = 0; i < 4; i++)
        ((float4*)dstp)[i] = make_float4(o[4*i], o[4*i+1], o[4*i+2], o[4*i+3]);
}

// ---------------- layer 2: agg(h1) -> @W2 -> +b2 -> leaky -> +h1 -> h2 -----
__global__ __launch_bounds__(256) void k_layer2(
    const float* __restrict__ W2, const float* __restrict__ b2)
{
    __shared__ float Ws[HID * HID];       // 16 KB
    __shared__ float aggs[BATCH * 68];    // [64][64+4pad] ~17.4 KB
    const int n = blockIdx.x, t = threadIdx.x;
    #pragma unroll
    for (int i = 0; i < 4; i++)
        ((float4*)Ws)[t + 256 * i] = ((const float4*)W2)[t + 256 * i];

    // gather: coalesced float4s; thread t, chunk i -> floats [4t+1024i, +4)
    float4 acc[4];
    #pragma unroll
    for (int i = 0; i < 4; i++) acc[i] = make_float4(0.f, 0.f, 0.f, 0.f);
    const int e0 = g_rowptr[n], e1 = g_rowptr[n + 1];
    int e = e0;
    for (; e + 1 < e1; e += 2) {
        int   s0 = g_col[e],  s1 = g_col[e + 1];
        float w0 = g_w[e],    w1 = g_w[e + 1];
        const float4* p0 = (const float4*)(g_h1 + (size_t)s0 * ROWF);
        const float4* p1 = (const float4*)(g_h1 + (size_t)s1 * ROWF);
        float4 u0 = p0[t],       u1 = p0[t + 256], u2 = p0[t + 512], u3 = p0[t + 768];
        float4 v0 = p1[t],       v1 = p1[t + 256], v2 = p1[t + 512], v3 = p1[t + 768];
        fma4(acc[0], w0, u0); fma4(acc[1], w0, u1); fma4(acc[2], w0, u2); fma4(acc[3], w0, u3);
        fma4(acc[0], w1, v0); fma4(acc[1], w1, v1); fma4(acc[2], w1, v2); fma4(acc[3], w1, v3);
    }
    if (e < e1) {
        int s0 = g_col[e]; float w0 = g_w[e];
        const float4* p0 = (const float4*)(g_h1 + (size_t)s0 * ROWF);
        fma4(acc[0], w0, p0[t]);       fma4(acc[1], w0, p0[t + 256]);
        fma4(acc[2], w0, p0[t + 512]); fma4(acc[3], w0, p0[t + 768]);
    }
    // float idx 4t+1024i -> b = t/16 + 16i, k0 = (t%16)*4
    const int bb = t >> 4, k0 = (t & 15) * 4;
    #pragma unroll
    for (int i = 0; i < 4; i++)
        *(float4*)&aggs[(bb + 16 * i) * 68 + k0] = acc[i];
    __syncthreads();

    // GEMM 64->64 + bias + leaky + residual
    const int b = t >> 2, j0 = (t & 3) * 16;
    float o[16];
    #pragma unroll
    for (int i = 0; i < 16; i++) o[i] = 0.f;
    #pragma unroll
    for (int k = 0; k < HID; k++) {
        float a = aggs[b * 68 + k];
        const float4* wr = (const float4*)(Ws + k * HID + j0);
        FMA16(o, a, wr);
    }
    const float* h1p = g_h1 + (size_t)n * ROWF + b * HID + j0;
    float* h2p = g_h2 + (size_t)n * ROWF + b * HID + j0;
    #pragma unroll
    for (int i = 0; i < 4; i++) {
        float4 r = ((const float4*)h1p)[i];
        float4 ov;
        ov.x = lrelu(o[4*i + 0] + b2[j0 + 4*i + 0]) + r.x;
        ov.y = lrelu(o[4*i + 1] + b2[j0 + 4*i + 1]) + r.y;
        ov.z = lrelu(o[4*i + 2] + b2[j0 + 4*i + 2]) + r.z;
        ov.w = lrelu(o[4*i + 3] + b2[j0 + 4*i + 3]) + r.w;
        ((float4*)h2p)[i] = ov;
    }
}

// ----- layer 3 + final: agg(h2)->@W3->+b3->LN->leaky->+h1 = h3 ; tanh(h3@Wf+bf)->out
__global__ __launch_bounds__(256) void k_layer3(
    const float* __restrict__ W3, const float* __restrict__ b3,
    const float* __restrict__ g3, const float* __restrict__ be3,
    const float* __restrict__ Wf, const float* __restrict__ bf,
    float* __restrict__ out)
{
    __shared__ float Ws[HID * HID];
    __shared__ float Wfs[HID * HID];
    __shared__ float aggs[BATCH * 68];
    const int n = blockIdx.x, t = threadIdx.x;
    #pragma unroll
    for (int i = 0; i < 4; i++) {
        ((float4*)Ws)[t + 256 * i]  = ((const float4*)W3)[t + 256 * i];
        ((float4*)Wfs)[t + 256 * i] = ((const float4*)Wf)[t + 256 * i];
    }

    float4 acc[4];
    #pragma unroll
    for (int i = 0; i < 4; i++) acc[i] = make_float4(0.f, 0.f, 0.f, 0.f);
    const int e0 = g_rowptr[n], e1 = g_rowptr[n + 1];
    int e = e0;
    for (; e + 1 < e1; e += 2) {
        int   s0 = g_col[e],  s1 = g_col[e + 1];
        float w0 = g_w[e],    w1 = g_w[e + 1];
        const float4* p0 = (const float4*)(g_h2 + (size_t)s0 * ROWF);
        const float4* p1 = (const float4*)(g_h2 + (size_t)s1 * ROWF);
        float4 u0 = p0[t],       u1 = p0[t + 256], u2 = p0[t + 512], u3 = p0[t + 768];
        float4 v0 = p1[t],       v1 = p1[t + 256], v2 = p1[t + 512], v3 = p1[t + 768];
        fma4(acc[0], w0, u0); fma4(acc[1], w0, u1); fma4(acc[2], w0, u2); fma4(acc[3], w0, u3);
        fma4(acc[0], w1, v0); fma4(acc[1], w1, v1); fma4(acc[2], w1, v2); fma4(acc[3], w1, v3);
    }
    if (e < e1) {
        int s0 = g_col[e]; float w0 = g_w[e];
        const float4* p0 = (const float4*)(g_h2 + (size_t)s0 * ROWF);
        fma4(acc[0], w0, p0[t]);       fma4(acc[1], w0, p0[t + 256]);
        fma4(acc[2], w0, p0[t + 512]); fma4(acc[3], w0, p0[t + 768]);
    }
    const int bb = t >> 4, k0 = (t & 15) * 4;
    #pragma unroll
    for (int i = 0; i < 4; i++)
        *(float4*)&aggs[(bb + 16 * i) * 68 + k0] = acc[i];
    __syncthreads();

    const int b = t >> 2, j0 = (t & 3) * 16;
    float o[16];
    #pragma unroll
    for (int i = 0; i < 16; i++) o[i] = 0.f;
    #pragma unroll
    for (int k = 0; k < HID; k++) {
        float a = aggs[b * 68 + k];
        const float4* wr = (const float4*)(Ws + k * HID + j0);
        FMA16(o, a, wr);
    }
    #pragma unroll
    for (int i = 0; i < 16; i++) o[i] += b3[j0 + i];
    // LN
    float s1 = 0.f, s2 = 0.f;
    #pragma unroll
    for (int i = 0; i < 16; i++) { s1 += o[i]; s2 += o[i] * o[i]; }
    s1 += __shfl_xor_sync(0xffffffffu, s1, 1);
    s1 += __shfl_xor_sync(0xffffffffu, s1, 2);
    s2 += __shfl_xor_sync(0xffffffffu, s2, 1);
    s2 += __shfl_xor_sync(0xffffffffu, s2, 2);
    float mu  = s1 * (1.f / HID);
    float var = s2 * (1.f / HID) - mu * mu;
    float rs  = rsqrtf(var + 1e-5f);
    const float* h1p = g_h1 + (size_t)n * ROWF + b * HID + j0;
    #pragma unroll
    for (int i = 0; i < 4; i++) {
        float4 r = ((const float4*)h1p)[i];
        float rr[4] = {r.x, r.y, r.z, r.w};
        #pragma unroll
        for (int q = 0; q < 4; q++) {
            int ii = 4 * i + q;
            float v = (o[ii] - mu) * rs * g3[j0 + ii] + be3[j0 + ii];
            o[ii] = lrelu(v) + rr[q];     // h3
        }
    }
    __syncthreads();   // all reads of aggs (W3 GEMM) done before overwrite
    #pragma unroll
    for (int i = 0; i < 4; i++)
        *(float4*)&aggs[b * 68 + j0 + 4 * i] =
            make_float4(o[4*i], o[4*i+1], o[4*i+2], o[4*i+3]);
    __syncthreads();

    // final GEMM + tanh
    float o2[16];
    #pragma unroll
    for (int i = 0; i < 16; i++) o2[i] = 0.f;
    #pragma unroll
    for (int k = 0; k < HID; k++) {
        float a = aggs[b * 68 + k];
        const float4* wr = (const float4*)(Wfs + k * HID + j0);
        FMA16(o2, a, wr);
    }
    float* op = out + (size_t)b * (N_AREA * HID) + (size_t)n * HID + j0;
    #pragma unroll
    for (int i = 0; i < 4; i++) {
        float4 ov;
        ov.x = tanhf(o2[4*i + 0] + bf[j0 + 4*i + 0]);
        ov.y = tanhf(o2[4*i + 1] + bf[j0 + 4*i + 1]);
        ov.z = tanhf(o2[4*i + 2] + bf[j0 + 4*i + 2]);
        ov.w = tanhf(o2[4*i + 3] + bf[j0 + 4*i + 3]);
        ((float4*)op)[i] = ov;
    }
}

// ---------------- launch ----------------------------------------------------
extern "C" void kernel_launch(void* const* d_in, const int* in_sizes, int n_in,
                              void* d_out, int out_size)
{
    const float* state = (const float*)d_in[0];
    const int*   ei    = (const int*)d_in[1];
    // last 12 tensors are W1,b1,W2,b2,W3,b3,g1,be1,g3,be3,Wf,bf regardless of
    // whether the python scalars (batch_size/rej_rate/theta) are materialized
    const int wb = n_in - 12;
    const float* W1  = (const float*)d_in[wb + 0];
    const float* b1  = (const float*)d_in[wb + 1];
    const float* W2  = (const float*)d_in[wb + 2];
    const float* b2  = (const float*)d_in[wb + 3];
    const float* W3  = (const float*)d_in[wb + 4];
    const float* b3  = (const float*)d_in[wb + 5];
    const float* g1  = (const float*)d_in[wb + 6];
    const float* be1 = (const float*)d_in[wb + 7];
    const float* g3  = (const float*)d_in[wb + 8];
    const float* be3 = (const float*)d_in[wb + 9];
    const float* Wf  = (const float*)d_in[wb + 10];
    const float* bf  = (const float*)d_in[wb + 11];
    float* out = (float*)d_out;

    k_initdeg<<<(N_AREA + 255) / 256, 256>>>();
    k_count  <<<(N_EDGE + 255) / 256, 256>>>(ei);
    k_dinv   <<<(N_AREA + 255) / 256, 256>>>();
    k_scan   <<<1, 1024>>>();
    k_fill   <<<(ETOT + 255) / 256, 256>>>(ei);
    k_layer1 <<<N_AREA, 256>>>(state, W1, b1, g1, be1);
    k_layer2 <<<N_AREA, 256>>>(W2, b2);
    k_layer3 <<<N_AREA, 256>>>(W3, b3, g3, be3, Wf, bf, out);
}

// round 5
// speedup vs baseline: 2.1925x; 2.1925x over previous
#include <cuda_runtime.h>
#include <math.h>

#define N_AREA 10000
#define N_FEAT 16
#define HID    64
#define N_EDGE 320000
#define BATCH  64
#define ETOT   (N_EDGE + N_AREA)
#define CHB    16                    /* batch chunk */
#define NCHUNK (BATCH / CHB)
#define CROW   (CHB * HID)           /* 1024 floats per node row per chunk */
#define STATE_ROW (N_AREA * N_FEAT)

// ---------------- scratch (device globals; no allocations allowed) ----------
__device__ int   g_deg[N_AREA];
__device__ float g_dinv[N_AREA];
__device__ int   g_rowptr[N_AREA + 1];
__device__ int   g_cursor[N_AREA];
__device__ int   g_col[ETOT];
__device__ float g_w[ETOT];
__device__ __align__(16) float g_h1[(size_t)N_AREA * CROW];   // 41 MB
__device__ __align__(16) float g_h2[(size_t)N_AREA * CROW];   // 41 MB

typedef unsigned long long ull;
__device__ __forceinline__ ull pack2(float x, float y) {
    ull r; asm("mov.b64 %0, {%1,%2};" : "=l"(r) : "f"(x), "f"(y)); return r;
}
__device__ __forceinline__ void unpack2(ull v, float& x, float& y) {
    asm("mov.b64 {%0,%1}, %2;" : "=f"(x), "=f"(y) : "l"(v));
}
__device__ __forceinline__ void fma2(ull& d, ull a, ull b) {
    asm("fma.rn.f32x2 %0, %1, %2, %0;" : "+l"(d) : "l"(a), "l"(b));
}
__device__ __forceinline__ float lrelu(float x) { return x >= 0.f ? x : 0.01f * x; }

// ---------------- CSR / norm construction ----------------------------------
__global__ void k_initdeg() {
    int i = blockIdx.x * blockDim.x + threadIdx.x;
    if (i < N_AREA) g_deg[i] = 1;   // self-loop
}
__global__ void k_count(const int* __restrict__ ei) {
    int e = blockIdx.x * blockDim.x + threadIdx.x;
    if (e < N_EDGE) atomicAdd(&g_deg[ei[N_EDGE + e]], 1);
}
__global__ void k_dinv() {
    int i = blockIdx.x * blockDim.x + threadIdx.x;
    if (i < N_AREA) g_dinv[i] = rsqrtf((float)g_deg[i]);
}
__global__ void k_scan() {
    __shared__ int wsum[32];
    __shared__ int btot_s;
    int tid = threadIdx.x, lane = tid & 31, wid = tid >> 5;
    int offset = 0;
    for (int base = 0; base < N_AREA; base += 1024) {
        int i = base + tid;
        int v = (i < N_AREA) ? g_deg[i] : 0;
        int x = v;
        #pragma unroll
        for (int d = 1; d < 32; d <<= 1) {
            int y = __shfl_up_sync(0xffffffffu, x, d);
            if (lane >= d) x += y;
        }
        if (lane == 31) wsum[wid] = x;
        __syncthreads();
        if (wid == 0) {
            int s = wsum[lane];
            #pragma unroll
            for (int d = 1; d < 32; d <<= 1) {
                int y = __shfl_up_sync(0xffffffffu, s, d);
                if (lane >= d) s += y;
            }
            wsum[lane] = s;
            if (lane == 31) btot_s = s;
        }
        __syncthreads();
        int incl = x + (wid > 0 ? wsum[wid - 1] : 0) + offset;
        if (i < N_AREA) { g_rowptr[i + 1] = incl; g_cursor[i] = incl - v; }
        offset += btot_s;
        __syncthreads();
    }
    if (tid == 0) g_rowptr[0] = 0;
}
__global__ void k_fill(const int* __restrict__ ei) {
    int e = blockIdx.x * blockDim.x + threadIdx.x;
    if (e < N_EDGE) {
        int s = ei[e], d = ei[N_EDGE + e];
        int pos = atomicAdd(&g_cursor[d], 1);
        g_col[pos] = s;
        g_w[pos] = g_dinv[s] * g_dinv[d];
    } else if (e < ETOT) {
        int n = e - N_EDGE;
        int pos = atomicAdd(&g_cursor[n], 1);
        g_col[pos] = n;
        float dv = g_dinv[n];
        g_w[pos] = dv * dv;
    }
}

// ------- layer 1 (per chunk): agg(x)->@W1->+b1->LN->leaky -> g_h1 ----------
__global__ __launch_bounds__(256) void k_layer1(
    const float* __restrict__ state, const float* __restrict__ W1,
    const float* __restrict__ b1v, const float* __restrict__ g1,
    const float* __restrict__ be1, int b0)
{
    __shared__ float W1s[N_FEAT * HID];   // 1024 floats
    __shared__ float aggs[CHB * 17];      // [16 b][16 f + pad]
    const int n = blockIdx.x, t = threadIdx.x;
    ((float4*)W1s)[t] = ((const float4*)W1)[t];

    const int b = t >> 4, f = t & 15;
    const float* __restrict__ base = state + (size_t)(b0 + b) * STATE_ROW + f;
    float acc = 0.f;
    const int e0 = g_rowptr[n], e1 = g_rowptr[n + 1];
    int e = e0;
    for (; e + 3 < e1; e += 4) {
        int s0 = g_col[e], s1 = g_col[e+1], s2 = g_col[e+2], s3 = g_col[e+3];
        float w0 = g_w[e], w1 = g_w[e+1], w2 = g_w[e+2], w3 = g_w[e+3];
        float v0 = base[s0 * 16], v1 = base[s1 * 16];
        float v2 = base[s2 * 16], v3 = base[s3 * 16];
        acc = fmaf(w0, v0, acc); acc = fmaf(w1, v1, acc);
        acc = fmaf(w2, v2, acc); acc = fmaf(w3, v3, acc);
    }
    for (; e < e1; e++) acc = fmaf(g_w[e], base[g_col[e] * 16], acc);
    aggs[b * 17 + f] = acc;
    __syncthreads();

    // GEMM 16->64: thread -> (b, j0 = (t&15)*4)
    const int jq = f;
    ull o0 = 0ull, o1 = 0ull;
    #pragma unroll
    for (int ff = 0; ff < N_FEAT; ff++) {
        float a = aggs[b * 17 + ff];
        ull aa = pack2(a, a);
        ulonglong2 w = ((const ulonglong2*)W1s)[ff * 16 + jq];
        fma2(o0, aa, w.x); fma2(o1, aa, w.y);
    }
    float o[4];
    unpack2(o0, o[0], o[1]); unpack2(o1, o[2], o[3]);
    float4 bb = ((const float4*)b1v)[jq];
    o[0] += bb.x; o[1] += bb.y; o[2] += bb.z; o[3] += bb.w;
    float sm1 = o[0] + o[1] + o[2] + o[3];
    float sm2 = o[0]*o[0] + o[1]*o[1] + o[2]*o[2] + o[3]*o[3];
    #pragma unroll
    for (int d = 1; d < 16; d <<= 1) {
        sm1 += __shfl_xor_sync(0xffffffffu, sm1, d);
        sm2 += __shfl_xor_sync(0xffffffffu, sm2, d);
    }
    float mu  = sm1 * (1.f / HID);
    float var = sm2 * (1.f / HID) - mu * mu;
    float rs  = rsqrtf(var + 1e-5f);
    float4 gg = ((const float4*)g1)[jq], ee = ((const float4*)be1)[jq];
    float4 ov;
    ov.x = lrelu((o[0] - mu) * rs * gg.x + ee.x);
    ov.y = lrelu((o[1] - mu) * rs * gg.y + ee.y);
    ov.z = lrelu((o[2] - mu) * rs * gg.z + ee.z);
    ov.w = lrelu((o[3] - mu) * rs * gg.w + ee.w);
    *(float4*)(g_h1 + (size_t)n * CROW + b * HID + jq * 4) = ov;
}

// ------- layer 2 (per chunk): agg(h1)->@W2->+b2->leaky->+h1 -> g_h2 --------
__global__ __launch_bounds__(256) void k_layer2(
    const float* __restrict__ W2, const float* __restrict__ b2v)
{
    __shared__ float Ws[HID * HID];       // 16 KB
    __shared__ float aggs[CHB * 68];      // [16 b][64 + pad]
    const int n = blockIdx.x, t = threadIdx.x;
    #pragma unroll
    for (int i = 0; i < 4; i++)
        ((float4*)Ws)[t + 256 * i] = ((const float4*)W2)[t + 256 * i];

    // gather: thread t owns float4 index t of the 4KB row (b = t>>4, h = (t&15)*4)
    ull a0 = 0ull, a1 = 0ull;
    const int e0 = g_rowptr[n], e1 = g_rowptr[n + 1];
    int e = e0;
    for (; e + 3 < e1; e += 4) {
        int s0 = g_col[e], s1 = g_col[e+1], s2 = g_col[e+2], s3 = g_col[e+3];
        float w0 = g_w[e], w1 = g_w[e+1], w2 = g_w[e+2], w3 = g_w[e+3];
        ulonglong2 v0 = ((const ulonglong2*)(g_h1 + (size_t)s0 * CROW))[t];
        ulonglong2 v1 = ((const ulonglong2*)(g_h1 + (size_t)s1 * CROW))[t];
        ulonglong2 v2 = ((const ulonglong2*)(g_h1 + (size_t)s2 * CROW))[t];
        ulonglong2 v3 = ((const ulonglong2*)(g_h1 + (size_t)s3 * CROW))[t];
        ull ww0 = pack2(w0, w0), ww1 = pack2(w1, w1);
        ull ww2 = pack2(w2, w2), ww3 = pack2(w3, w3);
        fma2(a0, ww0, v0.x); fma2(a1, ww0, v0.y);
        fma2(a0, ww1, v1.x); fma2(a1, ww1, v1.y);
        fma2(a0, ww2, v2.x); fma2(a1, ww2, v2.y);
        fma2(a0, ww3, v3.x); fma2(a1, ww3, v3.y);
    }
    for (; e < e1; e++) {
        int s0 = g_col[e]; float w0 = g_w[e];
        ulonglong2 v0 = ((const ulonglong2*)(g_h1 + (size_t)s0 * CROW))[t];
        ull ww0 = pack2(w0, w0);
        fma2(a0, ww0, v0.x); fma2(a1, ww0, v0.y);
    }
    const int b = t >> 4, hq = t & 15;
    {
        float f0, f1, f2, f3;
        unpack2(a0, f0, f1); unpack2(a1, f2, f3);
        *(float4*)&aggs[b * 68 + hq * 4] = make_float4(f0, f1, f2, f3);
    }
    __syncthreads();

    // GEMM 64->64 + bias + leaky + residual
    const int jq = hq;
    ull o0 = 0ull, o1 = 0ull;
    #pragma unroll
    for (int k = 0; k < HID; k++) {
        float a = aggs[b * 68 + k];
        ull aa = pack2(a, a);
        ulonglong2 w = ((const ulonglong2*)Ws)[k * 16 + jq];
        fma2(o0, aa, w.x); fma2(o1, aa, w.y);
    }
    float o[4];
    unpack2(o0, o[0], o[1]); unpack2(o1, o[2], o[3]);
    float4 bb = ((const float4*)b2v)[jq];
    float4 r = *(const float4*)(g_h1 + (size_t)n * CROW + b * HID + jq * 4);
    float4 ov;
    ov.x = lrelu(o[0] + bb.x) + r.x;
    ov.y = lrelu(o[1] + bb.y) + r.y;
    ov.z = lrelu(o[2] + bb.z) + r.z;
    ov.w = lrelu(o[3] + bb.w) + r.w;
    *(float4*)(g_h2 + (size_t)n * CROW + b * HID + jq * 4) = ov;
}

// ---- layer 3 + final (per chunk): agg(h2)->@W3->+b3->LN->leaky->+h1 = h3;
//      out = tanh(h3@Wf+bf)  (h3 never hits DRAM) ---------------------------
__global__ __launch_bounds__(256) void k_layer3(
    const float* __restrict__ W3, const float* __restrict__ b3v,
    const float* __restrict__ g3, const float* __restrict__ be3,
    const float* __restrict__ Wf, const float* __restrict__ bfv,
    float* __restrict__ out, int b0)
{
    __shared__ float Ws[HID * HID];
    __shared__ float Wfs[HID * HID];
    __shared__ float aggs[CHB * 68];
    const int n = blockIdx.x, t = threadIdx.x;
    #pragma unroll
    for (int i = 0; i < 4; i++) {
        ((float4*)Ws)[t + 256 * i]  = ((const float4*)W3)[t + 256 * i];
        ((float4*)Wfs)[t + 256 * i] = ((const float4*)Wf)[t + 256 * i];
    }

    ull a0 = 0ull, a1 = 0ull;
    const int e0 = g_rowptr[n], e1 = g_rowptr[n + 1];
    int e = e0;
    for (; e + 3 < e1; e += 4) {
        int s0 = g_col[e], s1 = g_col[e+1], s2 = g_col[e+2], s3 = g_col[e+3];
        float w0 = g_w[e], w1 = g_w[e+1], w2 = g_w[e+2], w3 = g_w[e+3];
        ulonglong2 v0 = ((const ulonglong2*)(g_h2 + (size_t)s0 * CROW))[t];
        ulonglong2 v1 = ((const ulonglong2*)(g_h2 + (size_t)s1 * CROW))[t];
        ulonglong2 v2 = ((const ulonglong2*)(g_h2 + (size_t)s2 * CROW))[t];
        ulonglong2 v3 = ((const ulonglong2*)(g_h2 + (size_t)s3 * CROW))[t];
        ull ww0 = pack2(w0, w0), ww1 = pack2(w1, w1);
        ull ww2 = pack2(w2, w2), ww3 = pack2(w3, w3);
        fma2(a0, ww0, v0.x); fma2(a1, ww0, v0.y);
        fma2(a0, ww1, v1.x); fma2(a1, ww1, v1.y);
        fma2(a0, ww2, v2.x); fma2(a1, ww2, v2.y);
        fma2(a0, ww3, v3.x); fma2(a1, ww3, v3.y);
    }
    for (; e < e1; e++) {
        int s0 = g_col[e]; float w0 = g_w[e];
        ulonglong2 v0 = ((const ulonglong2*)(g_h2 + (size_t)s0 * CROW))[t];
        ull ww0 = pack2(w0, w0);
        fma2(a0, ww0, v0.x); fma2(a1, ww0, v0.y);
    }
    const int b = t >> 4, hq = t & 15;
    {
        float f0, f1, f2, f3;
        unpack2(a0, f0, f1); unpack2(a1, f2, f3);
        *(float4*)&aggs[b * 68 + hq * 4] = make_float4(f0, f1, f2, f3);
    }
    __syncthreads();

    const int jq = hq;
    ull o0 = 0ull, o1 = 0ull;
    #pragma unroll
    for (int k = 0; k < HID; k++) {
        float a = aggs[b * 68 + k];
        ull aa = pack2(a, a);
        ulonglong2 w = ((const ulonglong2*)Ws)[k * 16 + jq];
        fma2(o0, aa, w.x); fma2(o1, aa, w.y);
    }
    float o[4];
    unpack2(o0, o[0], o[1]); unpack2(o1, o[2], o[3]);
    float4 bb = ((const float4*)b3v)[jq];
    o[0] += bb.x; o[1] += bb.y; o[2] += bb.z; o[3] += bb.w;
    // LN over 64 (16 lanes x 4)
    float sm1 = o[0] + o[1] + o[2] + o[3];
    float sm2 = o[0]*o[0] + o[1]*o[1] + o[2]*o[2] + o[3]*o[3];
    #pragma unroll
    for (int d = 1; d < 16; d <<= 1) {
        sm1 += __shfl_xor_sync(0xffffffffu, sm1, d);
        sm2 += __shfl_xor_sync(0xffffffffu, sm2, d);
    }
    float mu  = sm1 * (1.f / HID);
    float var = sm2 * (1.f / HID) - mu * mu;
    float rs  = rsqrtf(var + 1e-5f);
    float4 gg = ((const float4*)g3)[jq], ee = ((const float4*)be3)[jq];
    float4 r = *(const float4*)(g_h1 + (size_t)n * CROW + b * HID + jq * 4);
    o[0] = lrelu((o[0] - mu) * rs * gg.x + ee.x) + r.x;   // h3
    o[1] = lrelu((o[1] - mu) * rs * gg.y + ee.y) + r.y;
    o[2] = lrelu((o[2] - mu) * rs * gg.z + ee.z) + r.z;
    o[3] = lrelu((o[3] - mu) * rs * gg.w + ee.w) + r.w;

    __syncthreads();   // all W3-GEMM reads of aggs done before overwrite
    *(float4*)&aggs[b * 68 + jq * 4] = make_float4(o[0], o[1], o[2], o[3]);
    __syncthreads();

    // final GEMM + tanh
    ull q0 = 0ull, q1 = 0ull;
    #pragma unroll
    for (int k = 0; k < HID; k++) {
        float a = aggs[b * 68 + k];
        ull aa = pack2(a, a);
        ulonglong2 w = ((const ulonglong2*)Wfs)[k * 16 + jq];
        fma2(q0, aa, w.x); fma2(q1, aa, w.y);
    }
    float o2[4];
    unpack2(q0, o2[0], o2[1]); unpack2(q1, o2[2], o2[3]);
    float4 bf4 = ((const float4*)bfv)[jq];
    float* op = out + (size_t)(b0 + b) * (N_AREA * HID) + (size_t)n * HID + jq * 4;
    float4 ov;
    ov.x = tanhf(o2[0] + bf4.x);
    ov.y = tanhf(o2[1] + bf4.y);
    ov.z = tanhf(o2[2] + bf4.z);
    ov.w = tanhf(o2[3] + bf4.w);
    *(float4*)op = ov;
}

// ---------------- launch ----------------------------------------------------
extern "C" void kernel_launch(void* const* d_in, const int* in_sizes, int n_in,
                              void* d_out, int out_size)
{
    const float* state = (const float*)d_in[0];
    const int*   ei    = (const int*)d_in[1];
    const int wb = n_in - 12;
    const float* W1  = (const float*)d_in[wb + 0];
    const float* b1  = (const float*)d_in[wb + 1];
    const float* W2  = (const float*)d_in[wb + 2];
    const float* b2  = (const float*)d_in[wb + 3];
    const float* W3  = (const float*)d_in[wb + 4];
    const float* b3  = (const float*)d_in[wb + 5];
    const float* g1  = (const float*)d_in[wb + 6];
    const float* be1 = (const float*)d_in[wb + 7];
    const float* g3  = (const float*)d_in[wb + 8];
    const float* be3 = (const float*)d_in[wb + 9];
    const float* Wf  = (const float*)d_in[wb + 10];
    const float* bf  = (const float*)d_in[wb + 11];
    float* out = (float*)d_out;

    k_initdeg<<<(N_AREA + 255) / 256, 256>>>();
    k_count  <<<(N_EDGE + 255) / 256, 256>>>(ei);
    k_dinv   <<<(N_AREA + 255) / 256, 256>>>();
    k_scan   <<<1, 1024>>>();
    k_fill   <<<(ETOT + 255) / 256, 256>>>(ei);

    for (int cb = 0; cb < NCHUNK; cb++) {
        const int b0 = cb * CHB;
        k_layer1<<<N_AREA, 256>>>(state, W1, b1, g1, be1, b0);
        k_layer2<<<N_AREA, 256>>>(W2, b2);
        k_layer3<<<N_AREA, 256>>>(W3, b3, g3, be3, Wf, bf, out, b0);
    }
}

// round 7
// speedup vs baseline: 3.4000x; 1.5507x over previous
#include <cuda_runtime.h>
#include <cuda_fp16.h>
#include <math.h>

#define N_AREA 10000
#define N_FEAT 16
#define HID    64
#define N_EDGE 320000
#define BATCH  64
#define ETOT   (N_EDGE + N_AREA)
#define CHB    16                     /* batch chunk */
#define NCHUNK (BATCH / CHB)
#define HROW   256                    /* uint2 (4 halfs) per node row: 16*64/4 */
#define STATE_ROW (N_AREA * N_FEAT)

// ---------------- scratch (device globals; no allocations allowed) ----------
__device__ int   g_deg[N_AREA];
__device__ float g_dinv[N_AREA];
__device__ int   g_rowptr[N_AREA + 1];
__device__ int   g_cursor[N_AREA];
__device__ int2  g_cw[ETOT];                       // (src, weight-bits)
__device__ uint2 g_h1h[(size_t)N_AREA * HROW];     // fp16, 20.5 MB
__device__ uint2 g_h2h[(size_t)N_AREA * HROW];     // fp16, 20.5 MB

typedef unsigned long long ull;
__device__ __forceinline__ ull pack2(float x, float y) {
    ull r; asm("mov.b64 %0, {%1,%2};" : "=l"(r) : "f"(x), "f"(y)); return r;
}
__device__ __forceinline__ void unpack2(ull v, float& x, float& y) {
    asm("mov.b64 {%0,%1}, %2;" : "=f"(x), "=f"(y) : "l"(v));
}
__device__ __forceinline__ void fma2(ull& d, ull a, ull b) {
    asm("fma.rn.f32x2 %0, %1, %2, %0;" : "+l"(d) : "l"(a), "l"(b));
}
__device__ __forceinline__ float lrelu(float x) { return x >= 0.f ? x : 0.01f * x; }

__device__ __forceinline__ void hfma(float4& a, float w, uint2 v) {
    float2 lo = __half22float2(*(const __half2*)&v.x);
    float2 hi = __half22float2(*(const __half2*)&v.y);
    a.x = fmaf(w, lo.x, a.x); a.y = fmaf(w, lo.y, a.y);
    a.z = fmaf(w, hi.x, a.z); a.w = fmaf(w, hi.y, a.w);
}
__device__ __forceinline__ uint2 to_h4(float v0, float v1, float v2, float v3) {
    uint2 r;
    __half2 a = __floats2half2_rn(v0, v1);
    __half2 b = __floats2half2_rn(v2, v3);
    r.x = *(unsigned*)&a; r.y = *(unsigned*)&b;
    return r;
}
__device__ __forceinline__ void from_h4(uint2 v, float& v0, float& v1, float& v2, float& v3) {
    float2 lo = __half22float2(*(const __half2*)&v.x);
    float2 hi = __half22float2(*(const __half2*)&v.y);
    v0 = lo.x; v1 = lo.y; v2 = hi.x; v3 = hi.y;
}

// ---------------- CSR / norm construction ----------------------------------
__global__ void k_initdeg() {
    int i = blockIdx.x * blockDim.x + threadIdx.x;
    if (i < N_AREA) g_deg[i] = 1;   // self-loop
}
__global__ void k_count(const int* __restrict__ ei) {
    int e = blockIdx.x * blockDim.x + threadIdx.x;
    if (e < N_EDGE) atomicAdd(&g_deg[ei[N_EDGE + e]], 1);
}
__global__ void k_dinv() {
    int i = blockIdx.x * blockDim.x + threadIdx.x;
    if (i < N_AREA) g_dinv[i] = rsqrtf((float)g_deg[i]);
}
__global__ void k_scan() {
    __shared__ int wsum[32];
    __shared__ int btot_s;
    int tid = threadIdx.x, lane = tid & 31, wid = tid >> 5;
    int offset = 0;
    for (int base = 0; base < N_AREA; base += 1024) {
        int i = base + tid;
        int v = (i < N_AREA) ? g_deg[i] : 0;
        int x = v;
        #pragma unroll
        for (int d = 1; d < 32; d <<= 1) {
            int y = __shfl_up_sync(0xffffffffu, x, d);
            if (lane >= d) x += y;
        }
        if (lane == 31) wsum[wid] = x;
        __syncthreads();
        if (wid == 0) {
            int s = wsum[lane];
            #pragma unroll
            for (int d = 1; d < 32; d <<= 1) {
                int y = __shfl_up_sync(0xffffffffu, s, d);
                if (lane >= d) s += y;
            }
            wsum[lane] = s;
            if (lane == 31) btot_s = s;
        }
        __syncthreads();
        int incl = x + (wid > 0 ? wsum[wid - 1] : 0) + offset;
        if (i < N_AREA) { g_rowptr[i + 1] = incl; g_cursor[i] = incl - v; }
        offset += btot_s;
        __syncthreads();
    }
    if (tid == 0) g_rowptr[0] = 0;
}
__global__ void k_fill(const int* __restrict__ ei) {
    int e = blockIdx.x * blockDim.x + threadIdx.x;
    if (e < N_EDGE) {
        int s = ei[e], d = ei[N_EDGE + e];
        int pos = atomicAdd(&g_cursor[d], 1);
        g_cw[pos] = make_int2(s, __float_as_int(g_dinv[s] * g_dinv[d]));
    } else if (e < ETOT) {
        int n = e - N_EDGE;
        int pos = atomicAdd(&g_cursor[n], 1);
        float dv = g_dinv[n];
        g_cw[pos] = make_int2(n, __float_as_int(dv * dv));
    }
}

// register-blocked 64x64 GEMM core: 64 threads, thread (bg,jq) -> 4b x 4j.
// aggs stride 68 floats, W in smem as [64][64] floats. Results in o[4][2] f32x2.
#define GEMM64(o, aggsp, Wsp) do { \
    const ulonglong2* wr_ = (const ulonglong2*)(Wsp); \
    _Pragma("unroll") \
    for (int k4 = 0; k4 < HID; k4 += 4) { \
        float4 a4_[4]; \
        _Pragma("unroll") \
        for (int i_ = 0; i_ < 4; i_++) \
            a4_[i_] = *(const float4*)&(aggsp)[(bg * 4 + i_) * 68 + k4]; \
        _Pragma("unroll") \
        for (int kk_ = 0; kk_ < 4; kk_++) { \
            ulonglong2 w_ = wr_[(k4 + kk_) * 16 + jq]; \
            _Pragma("unroll") \
            for (int i_ = 0; i_ < 4; i_++) { \
                float a_ = (&a4_[i_].x)[kk_]; \
                ull aa_ = pack2(a_, a_); \
                fma2((o)[i_][0], aa_, w_.x); \
                fma2((o)[i_][1], aa_, w_.y); \
            } \
        } \
    } \
} while (0)

// ------- layer 1 (per chunk): agg(x)->@W1->+b1->LN->leaky -> g_h1h ---------
__global__ __launch_bounds__(256) void k_layer1(
    const float* __restrict__ state, const float* __restrict__ W1,
    const float* __restrict__ b1v, const float* __restrict__ g1,
    const float* __restrict__ be1, int b0)
{
    __shared__ float W1s[N_FEAT * HID];
    __shared__ float aggs[CHB * 16];      // stride 16, K=16
    __shared__ int2  s_cw[128];
    const int n = blockIdx.x, t = threadIdx.x;
    ((float4*)W1s)[t] = ((const float4*)W1)[t];

    const int b = t >> 4, f = t & 15;
    const float* __restrict__ base = state + (size_t)(b0 + b) * STATE_ROW + f;
    float acc = 0.f;
    const int e0 = g_rowptr[n], e1 = g_rowptr[n + 1];
    for (int eb = e0; eb < e1; eb += 128) {
        const int m = min(128, e1 - eb);
        __syncthreads();
        if (t < m) s_cw[t] = g_cw[eb + t];
        __syncthreads();
        int i = 0;
        for (; i + 3 < m; i += 4) {
            int2 c0 = s_cw[i], c1 = s_cw[i+1], c2 = s_cw[i+2], c3 = s_cw[i+3];
            float v0 = base[c0.x * 16], v1 = base[c1.x * 16];
            float v2 = base[c2.x * 16], v3 = base[c3.x * 16];
            acc = fmaf(__int_as_float(c0.y), v0, acc);
            acc = fmaf(__int_as_float(c1.y), v1, acc);
            acc = fmaf(__int_as_float(c2.y), v2, acc);
            acc = fmaf(__int_as_float(c3.y), v3, acc);
        }
        for (; i < m; i++) {
            int2 c = s_cw[i];
            acc = fmaf(__int_as_float(c.y), base[c.x * 16], acc);
        }
    }
    aggs[b * 16 + f] = acc;
    __syncthreads();

    if (t < 64) {
        const int bg = t >> 4, jq = t & 15;
        ull o[4][2] = {{0ull,0ull},{0ull,0ull},{0ull,0ull},{0ull,0ull}};
        const ulonglong2* wr = (const ulonglong2*)W1s;
        #pragma unroll
        for (int k4 = 0; k4 < N_FEAT; k4 += 4) {
            float4 a4[4];
            #pragma unroll
            for (int i = 0; i < 4; i++)
                a4[i] = *(const float4*)&aggs[(bg * 4 + i) * 16 + k4];
            #pragma unroll
            for (int kk = 0; kk < 4; kk++) {
                ulonglong2 w = wr[(k4 + kk) * 16 + jq];
                #pragma unroll
                for (int i = 0; i < 4; i++) {
                    float a = (&a4[i].x)[kk];
                    ull aa = pack2(a, a);
                    fma2(o[i][0], aa, w.x); fma2(o[i][1], aa, w.y);
                }
            }
        }
        float4 bb = ((const float4*)b1v)[jq];
        float4 gg = ((const float4*)g1)[jq];
        float4 ee = ((const float4*)be1)[jq];
        #pragma unroll
        for (int i = 0; i < 4; i++) {
            float v0, v1, v2, v3;
            unpack2(o[i][0], v0, v1); unpack2(o[i][1], v2, v3);
            v0 += bb.x; v1 += bb.y; v2 += bb.z; v3 += bb.w;
            float s1 = v0 + v1 + v2 + v3;
            float s2 = v0*v0 + v1*v1 + v2*v2 + v3*v3;
            #pragma unroll
            for (int d = 1; d < 16; d <<= 1) {
                s1 += __shfl_xor_sync(0xffffffffu, s1, d);
                s2 += __shfl_xor_sync(0xffffffffu, s2, d);
            }
            float mu  = s1 * (1.f / HID);
            float var = s2 * (1.f / HID) - mu * mu;
            float rs  = rsqrtf(var + 1e-5f);
            v0 = lrelu((v0 - mu) * rs * gg.x + ee.x);
            v1 = lrelu((v1 - mu) * rs * gg.y + ee.y);
            v2 = lrelu((v2 - mu) * rs * gg.z + ee.z);
            v3 = lrelu((v3 - mu) * rs * gg.w + ee.w);
            g_h1h[(size_t)n * HROW + (bg * 4 + i) * 16 + jq] = to_h4(v0, v1, v2, v3);
        }
    }
}

// ------- layer 2 (per chunk): agg(h1)->@W2->+b2->leaky->+h1 -> g_h2h -------
__global__ __launch_bounds__(256) void k_layer2(
    const float* __restrict__ W2, const float* __restrict__ b2v)
{
    __shared__ float Ws[HID * HID];
    __shared__ float aggs[CHB * 68];
    __shared__ int2  s_cw[128];
    const int n = blockIdx.x, t = threadIdx.x;
    #pragma unroll
    for (int i = 0; i < 4; i++)
        ((float4*)Ws)[t + 256 * i] = ((const float4*)W2)[t + 256 * i];

    float4 acc = make_float4(0.f, 0.f, 0.f, 0.f);
    const uint2* __restrict__ hb = g_h1h;
    const int e0 = g_rowptr[n], e1 = g_rowptr[n + 1];
    for (int eb = e0; eb < e1; eb += 128) {
        const int m = min(128, e1 - eb);
        __syncthreads();
        if (t < m) s_cw[t] = g_cw[eb + t];
        __syncthreads();
        int i = 0;
        for (; i + 3 < m; i += 4) {
            int2 c0 = s_cw[i], c1 = s_cw[i+1], c2 = s_cw[i+2], c3 = s_cw[i+3];
            uint2 v0 = hb[(size_t)c0.x * HROW + t];
            uint2 v1 = hb[(size_t)c1.x * HROW + t];
            uint2 v2 = hb[(size_t)c2.x * HROW + t];
            uint2 v3 = hb[(size_t)c3.x * HROW + t];
            hfma(acc, __int_as_float(c0.y), v0);
            hfma(acc, __int_as_float(c1.y), v1);
            hfma(acc, __int_as_float(c2.y), v2);
            hfma(acc, __int_as_float(c3.y), v3);
        }
        for (; i < m; i++) {
            int2 c = s_cw[i];
            hfma(acc, __int_as_float(c.y), hb[(size_t)c.x * HROW + t]);
        }
    }
    { const int b = t >> 4, hq = t & 15;
      *(float4*)&aggs[b * 68 + hq * 4] = acc; }
    __syncthreads();

    if (t < 64) {
        const int bg = t >> 4, jq = t & 15;
        ull o[4][2] = {{0ull,0ull},{0ull,0ull},{0ull,0ull},{0ull,0ull}};
        GEMM64(o, aggs, Ws);
        float4 bb = ((const float4*)b2v)[jq];
        #pragma unroll
        for (int i = 0; i < 4; i++) {
            float v0, v1, v2, v3;
            unpack2(o[i][0], v0, v1); unpack2(o[i][1], v2, v3);
            float r0, r1, r2, r3;
            from_h4(g_h1h[(size_t)n * HROW + (bg * 4 + i) * 16 + jq], r0, r1, r2, r3);
            v0 = lrelu(v0 + bb.x) + r0;
            v1 = lrelu(v1 + bb.y) + r1;
            v2 = lrelu(v2 + bb.z) + r2;
            v3 = lrelu(v3 + bb.w) + r3;
            g_h2h[(size_t)n * HROW + (bg * 4 + i) * 16 + jq] = to_h4(v0, v1, v2, v3);
        }
    }
}

// ---- layer 3 + final (per chunk): agg(h2)->@W3->+b3->LN->leaky->+h1 = h3;
//      out = tanh(h3@Wf+bf)  (h3 never hits DRAM) ---------------------------
__global__ __launch_bounds__(256) void k_layer3(
    const float* __restrict__ W3, const float* __restrict__ b3v,
    const float* __restrict__ g3, const float* __restrict__ be3,
    const float* __restrict__ Wf, const float* __restrict__ bfv,
    float* __restrict__ out, int b0)
{
    __shared__ float Ws[HID * HID];
    __shared__ float Wfs[HID * HID];
    __shared__ float aggs[CHB * 68];
    __shared__ float agg2[CHB * 68];
    __shared__ int2  s_cw[128];
    const int n = blockIdx.x, t = threadIdx.x;
    #pragma unroll
    for (int i = 0; i < 4; i++) {
        ((float4*)Ws)[t + 256 * i]  = ((const float4*)W3)[t + 256 * i];
        ((float4*)Wfs)[t + 256 * i] = ((const float4*)Wf)[t + 256 * i];
    }

    float4 acc = make_float4(0.f, 0.f, 0.f, 0.f);
    const uint2* __restrict__ hb = g_h2h;
    const int e0 = g_rowptr[n], e1 = g_rowptr[n + 1];
    for (int eb = e0; eb < e1; eb += 128) {
        const int m = min(128, e1 - eb);
        __syncthreads();
        if (t < m) s_cw[t] = g_cw[eb + t];
        __syncthreads();
        int i = 0;
        for (; i + 3 < m; i += 4) {
            int2 c0 = s_cw[i], c1 = s_cw[i+1], c2 = s_cw[i+2], c3 = s_cw[i+3];
            uint2 v0 = hb[(size_t)c0.x * HROW + t];
            uint2 v1 = hb[(size_t)c1.x * HROW + t];
            uint2 v2 = hb[(size_t)c2.x * HROW + t];
            uint2 v3 = hb[(size_t)c3.x * HROW + t];
            hfma(acc, __int_as_float(c0.y), v0);
            hfma(acc, __int_as_float(c1.y), v1);
            hfma(acc, __int_as_float(c2.y), v2);
            hfma(acc, __int_as_float(c3.y), v3);
        }
        for (; i < m; i++) {
            int2 c = s_cw[i];
            hfma(acc, __int_as_float(c.y), hb[(size_t)c.x * HROW + t]);
        }
    }
    { const int b = t >> 4, hq = t & 15;
      *(float4*)&aggs[b * 68 + hq * 4] = acc; }
    __syncthreads();

    const int bg = t >> 4, jq = t & 15;
    if (t < 64) {
        ull o[4][2] = {{0ull,0ull},{0ull,0ull},{0ull,0ull},{0ull,0ull}};
        GEMM64(o, aggs, Ws);
        float4 bb = ((const float4*)b3v)[jq];
        float4 gg = ((const float4*)g3)[jq];
        float4 ee = ((const float4*)be3)[jq];
        #pragma unroll
        for (int i = 0; i < 4; i++) {
            float v0, v1, v2, v3;
            unpack2(o[i][0], v0, v1); unpack2(o[i][1], v2, v3);
            v0 += bb.x; v1 += bb.y; v2 += bb.z; v3 += bb.w;
            float s1 = v0 + v1 + v2 + v3;
            float s2 = v0*v0 + v1*v1 + v2*v2 + v3*v3;
            #pragma unroll
            for (int d = 1; d < 16; d <<= 1) {
                s1 += __shfl_xor_sync(0xffffffffu, s1, d);
                s2 += __shfl_xor_sync(0xffffffffu, s2, d);
            }
            float mu  = s1 * (1.f / HID);
            float var = s2 * (1.f / HID) - mu * mu;
            float rs  = rsqrtf(var + 1e-5f);
            float r0, r1, r2, r3;
            from_h4(g_h1h[(size_t)n * HROW + (bg * 4 + i) * 16 + jq], r0, r1, r2, r3);
            v0 = lrelu((v0 - mu) * rs * gg.x + ee.x) + r0;
            v1 = lrelu((v1 - mu) * rs * gg.y + ee.y) + r1;
            v2 = lrelu((v2 - mu) * rs * gg.z + ee.z) + r2;
            v3 = lrelu((v3 - mu) * rs * gg.w + ee.w) + r3;
            *(float4*)&agg2[(bg * 4 + i) * 68 + jq * 4] = make_float4(v0, v1, v2, v3);
        }
    }
    __syncthreads();

    if (t < 64) {
        ull q[4][2] = {{0ull,0ull},{0ull,0ull},{0ull,0ull},{0ull,0ull}};
        GEMM64(q, agg2, Wfs);
        float4 bf4 = ((const float4*)bfv)[jq];
        #pragma unroll
        for (int i = 0; i < 4; i++) {
            float v0, v1, v2, v3;
            unpack2(q[i][0], v0, v1); unpack2(q[i][1], v2, v3);
            float4 ov;
            ov.x = tanhf(v0 + bf4.x);
            ov.y = tanhf(v1 + bf4.y);
            ov.z = tanhf(v2 + bf4.z);
            ov.w = tanhf(v3 + bf4.w);
            float* op = out + (size_t)(b0 + bg * 4 + i) * ((size_t)N_AREA * HID)
                            + (size_t)n * HID + jq * 4;
            *(float4*)op = ov;
        }
    }
}

// ---------------- launch ----------------------------------------------------
extern "C" void kernel_launch(void* const* d_in, const int* in_sizes, int n_in,
                              void* d_out, int out_size)
{
    const float* state = (const float*)d_in[0];
    const int*   ei    = (const int*)d_in[1];
    const int wb = n_in - 12;
    const float* W1  = (const float*)d_in[wb + 0];
    const float* b1  = (const float*)d_in[wb + 1];
    const float* W2  = (const float*)d_in[wb + 2];
    const float* b2  = (const float*)d_in[wb + 3];
    const float* W3  = (const float*)d_in[wb + 4];
    const float* b3  = (const float*)d_in[wb + 5];
    const float* g1  = (const float*)d_in[wb + 6];
    const float* be1 = (const float*)d_in[wb + 7];
    const float* g3  = (const float*)d_in[wb + 8];
    const float* be3 = (const float*)d_in[wb + 9];
    const float* Wf  = (const float*)d_in[wb + 10];
    const float* bf  = (const float*)d_in[wb + 11];
    float* out = (float*)d_out;

    k_initdeg<<<(N_AREA + 255) / 256, 256>>>();
    k_count  <<<(N_EDGE + 255) / 256, 256>>>(ei);
    k_dinv   <<<(N_AREA + 255) / 256, 256>>>();
    k_scan   <<<1, 1024>>>();
    k_fill   <<<(ETOT + 255) / 256, 256>>>(ei);

    for (int cb = 0; cb < NCHUNK; cb++) {
        const int b0 = cb * CHB;
        k_layer1<<<N_AREA, 256>>>(state, W1, b1, g1, be1, b0);
        k_layer2<<<N_AREA, 256>>>(W2, b2);
        k_layer3<<<N_AREA, 256>>>(W3, b3, g3, be3, Wf, bf, out, b0);
    }
}